// round 7
// baseline (speedup 1.0000x reference)
#include <cuda_runtime.h>
#include <stdint.h>
#include <stddef.h>

// ===========================================================================
// FARGAN vocoder. B=64, T=100, NSUB=4, S=64, HOP=256, IC=512.
// Stage 0: precompute ALL noise (partitionable threefry) -> g_nz
// Stage 1: input MLP for all frames (no recurrence)      -> g_X
// Stage 2: pack/transpose recurrent weights              -> g_wp
// Stage 3: sequential recurrent kernel, 32 CTAs x 384 thr, rows (b, b+32).
//          f32x2 packed FMA, shfl-fused reductions, overlapped noise staging.
// ===========================================================================

__device__ float g_A1[6400 * 512];
__device__ float g_H [6400 * 512];
__device__ float g_X [6400 * 256];
__device__ float4 g_wp[50176];       // packed transposed recurrent weights
__device__ uint2 g_kk[4000];
__device__ float g_nz[18022400];     // 400 steps * 45056 noise values

// packed-weight offsets (float4 units)
#define OFF_FW     0
#define OFF_FWGLU  2048
#define OFF_WIH1   3072
#define OFF_WHH1   9216
#define OFF_GLU1   12288
#define OFF_WIH2   13312
#define OFF_WHH2   19456
#define OFF_GLU2   22528
#define OFF_WIH3   23552
#define OFF_WHH3   29696
#define OFF_GLU3   32768
#define OFF_SKIPD  33792
#define OFF_SKIPG  44032
#define OFF_OUT    48128

// ----------------------------- threefry2x32 --------------------------------
__device__ __forceinline__ uint32_t rotl32(uint32_t v, int s) {
    return (v << s) | (v >> (32 - s));
}
__device__ __forceinline__ uint2 tf2x32(uint2 key, uint2 ctr) {
    uint32_t ks0 = key.x, ks1 = key.y;
    uint32_t ks2 = ks0 ^ ks1 ^ 0x1BD11BDAu;
    uint32_t x0 = ctr.x + ks0, x1 = ctr.y + ks1;
#define TFR(r) { x0 += x1; x1 = rotl32(x1, (r)); x1 ^= x0; }
    TFR(13) TFR(15) TFR(26) TFR(6)   x0 += ks1; x1 += ks2 + 1u;
    TFR(17) TFR(29) TFR(16) TFR(24)  x0 += ks2; x1 += ks0 + 2u;
    TFR(13) TFR(15) TFR(26) TFR(6)   x0 += ks0; x1 += ks1 + 3u;
    TFR(17) TFR(29) TFR(16) TFR(24)  x0 += ks1; x1 += ks2 + 4u;
    TFR(13) TFR(15) TFR(26) TFR(6)   x0 += ks2; x1 += ks0 + 5u;
#undef TFR
    return make_uint2(x0, x1);
}
__device__ __forceinline__ float nzf(uint32_t r) {
    float u = __uint_as_float((r >> 9) | 0x3f800000u) - 1.0f;
    return (u - 0.5f) * (1.0f / 127.0f);
}
__device__ __forceinline__ float clip1(float v) { return fminf(fmaxf(v, -1.0f), 1.0f); }
__device__ __forceinline__ float sigm(float x) { return 1.0f / (1.0f + expf(-x)); }

// ------------------------- noise precomputation ----------------------------
__global__ void gen_keys() {
    int idx = blockIdx.x * 128 + threadIdx.x;
    if (idx >= 4000) return;
    int step = idx / 10, q = idx % 10;
    uint2 fkey = tf2x32(make_uint2(0u, 1u), make_uint2(0u, (uint32_t)step));
    g_kk[idx] = tf2x32(fkey, make_uint2(0u, (uint32_t)q));
}
__global__ void gen_noise() {
    int rem = blockIdx.x * 256 + threadIdx.x;   // [0, 45056)
    int step = blockIdx.y;
    int q, f;
    if (rem < 36864) { q = rem >> 12; f = rem & 4095; }
    else             { q = 9;         f = rem - 36864; }
    uint2 kk = g_kk[step * 10 + q];
    uint2 c = tf2x32(kk, make_uint2(0u, (uint32_t)f));
    g_nz[(size_t)step * 45056 + rem] = nzf(c.x ^ c.y);
}

// ----------------------------- input MLP -----------------------------------
__global__ void build_a1(const float* __restrict__ feats, const float* __restrict__ gf) {
    int idx = blockIdx.x * blockDim.x + threadIdx.x;
    if (idx >= 6400 * 512) return;
    int row = idx >> 9;
    int k = idx & 511;
    int t = row >> 6, b = row & 63;
    float v;
    if (k < 256) v = feats[(b * 256 + k) * 100 + t];
    else         v = gf[b * 256 + (k - 256)];
    g_A1[idx] = v;
}

template <int ACT>
__device__ __forceinline__ void gemm_body(const float* __restrict__ A,
                                          const float* __restrict__ W,
                                          const float* __restrict__ bias,
                                          float* __restrict__ out, int N, int K) {
    __shared__ float As[64][17];
    __shared__ float Bs[16][65];
    const int bm = blockIdx.x * 64, bn = blockIdx.y * 64;
    const int tx = threadIdx.x & 15, ty = threadIdx.x >> 4;
    float acc[4][4] = {};
    for (int k0 = 0; k0 < K; k0 += 16) {
#pragma unroll
        for (int i = 0; i < 4; i++) {
            int lin = threadIdx.x + i * 256;
            int r = lin >> 4, c = lin & 15;
            As[r][c] = A[(bm + r) * K + k0 + c];
            Bs[c][r] = W[(bn + r) * K + k0 + c];
        }
        __syncthreads();
#pragma unroll
        for (int kk = 0; kk < 16; kk++) {
            float a[4], bb[4];
#pragma unroll
            for (int i = 0; i < 4; i++) a[i] = As[ty * 4 + i][kk];
#pragma unroll
            for (int j = 0; j < 4; j++) bb[j] = Bs[kk][tx * 4 + j];
#pragma unroll
            for (int i = 0; i < 4; i++)
#pragma unroll
                for (int j = 0; j < 4; j++)
                    acc[i][j] = fmaf(a[i], bb[j], acc[i][j]);
        }
        __syncthreads();
    }
#pragma unroll
    for (int i = 0; i < 4; i++) {
        int m = bm + ty * 4 + i;
#pragma unroll
        for (int j = 0; j < 4; j++) {
            int nn = bn + tx * 4 + j;
            float v = acc[i][j] + bias[nn];
            if (ACT) v = tanhf(v);
            out[m * N + nn] = v;
        }
    }
}
__global__ __launch_bounds__(256) void gemm1(const float* __restrict__ W,
                                             const float* __restrict__ b) {
    gemm_body<1>(g_A1, W, b, g_H, 512, 512);
}
__global__ __launch_bounds__(256) void gemm2(const float* __restrict__ W,
                                             const float* __restrict__ b) {
    gemm_body<0>(g_H, W, b, g_X, 256, 512);
}

// ----------------------- weight transpose/pack -----------------------------
__global__ void packw(const float* __restrict__ src, int off, int N, int K4) {
    int idx = blockIdx.x * blockDim.x + threadIdx.x;
    if (idx >= N * K4) return;
    int n = idx % N, kq = idx / N;
    const float* s = src + n * (K4 * 4) + 4 * kq;
    g_wp[off + idx] = make_float4(s[0], s[1], s[2], s[3]);
}

// ---------------------- packed f32x2 dual-row dot --------------------------
// wp pre-offset to segment; lanes of each f32x2 = (k, k+1) of SAME row, so the
// weight pair comes straight from the float4 load (no dup MOV).
// x0/x1: per-row activation arrays (8B-aligned at least).
template <int LEN>
__device__ __forceinline__ float2 dotp2(const float4* __restrict__ wp, int n, int N,
                                        const float* __restrict__ x0,
                                        const float* __restrict__ x1) {
    const ulonglong2* wv = reinterpret_cast<const ulonglong2*>(wp);
    const uint64_t* xa = reinterpret_cast<const uint64_t*>(x0);
    const uint64_t* xb = reinterpret_cast<const uint64_t*>(x1);
    uint64_t a0 = 0ull, a1 = 0ull, b0 = 0ull, b1 = 0ull;  // bits 0 == (0.f,0.f)
#pragma unroll
    for (int i = 0; i < LEN; i++) {
        ulonglong2 w = wv[i * N + n];
        uint64_t p0 = xa[2 * i], p1 = xa[2 * i + 1];
        uint64_t q0 = xb[2 * i], q1 = xb[2 * i + 1];
        asm("fma.rn.f32x2 %0, %1, %2, %0;" : "+l"(a0) : "l"(w.x), "l"(p0));
        asm("fma.rn.f32x2 %0, %1, %2, %0;" : "+l"(a1) : "l"(w.y), "l"(p1));
        asm("fma.rn.f32x2 %0, %1, %2, %0;" : "+l"(b0) : "l"(w.x), "l"(q0));
        asm("fma.rn.f32x2 %0, %1, %2, %0;" : "+l"(b1) : "l"(w.y), "l"(q1));
    }
    uint64_t s0, s1;
    asm("add.rn.f32x2 %0, %1, %2;" : "=l"(s0) : "l"(a0), "l"(a1));
    asm("add.rn.f32x2 %0, %1, %2;" : "=l"(s1) : "l"(b0), "l"(b1));
    uint32_t lo0, hi0, lo1, hi1;
    asm("mov.b64 {%0,%1}, %2;" : "=r"(lo0), "=r"(hi0) : "l"(s0));
    asm("mov.b64 {%0,%1}, %2;" : "=r"(lo1), "=r"(hi1) : "l"(s1));
    return make_float2(__uint_as_float(lo0) + __uint_as_float(hi0),
                       __uint_as_float(lo1) + __uint_as_float(hi1));
}

// warp reduce helpers (partners are adjacent lanes)
__device__ __forceinline__ float2 red2_1(float2 v) {
    v.x += __shfl_xor_sync(0xffffffffu, v.x, 1);
    v.y += __shfl_xor_sync(0xffffffffu, v.y, 1);
    return v;
}
__device__ __forceinline__ float2 red2_12(float2 v) {
    v.x += __shfl_xor_sync(0xffffffffu, v.x, 1);
    v.y += __shfl_xor_sync(0xffffffffu, v.y, 1);
    v.x += __shfl_xor_sync(0xffffffffu, v.x, 2);
    v.y += __shfl_xor_sync(0xffffffffu, v.y, 2);
    return v;
}

// --------------------------- recurrent kernel ------------------------------
__global__ __launch_bounds__(384, 1) void fargan_rnn(float* __restrict__ out) {
    const int tid = threadIdx.x;
    const int b0 = blockIdx.x;            // batch rows b0 and b0+32

    // split-row activation arrays: index [r][...] with r in {0,1}
    __shared__ __align__(16) float sfr[2][320];    // [g1|g2|g3|fw|prevn]
    __shared__ __align__(16) float fwin[2][128];   // [sub_noised | s3]
    __shared__ __align__(16) float tmp[2][64];
    __shared__ __align__(16) float h1[2][64], h2[2][64], h3[2][64];
    __shared__ __align__(16) float prev[2][64];
    __shared__ __align__(16) float skb[2][128];
    __shared__ __align__(16) float sk2[2][128];
    __shared__ __align__(16) float2 part_a[384], part_b[192];
    __shared__ __align__(16) float nbuf[1408];

    // staging of one step's noise into nbuf:
    //  nbuf: q<9 -> q*128 + r*64 + j ; q=9 -> 1152 + r*128 + j
#define STAGE_NOISE(STEP, BASE, STRIDE)                                        \
    {                                                                          \
        const float* nsrc = g_nz + (size_t)(STEP) * 45056;                     \
        for (int c = (BASE); c < 352; c += (STRIDE)) {                         \
            int rho = c >> 4, l = c & 15;                                      \
            int goff, soff;                                                    \
            if (rho < 18) {                                                    \
                int q = rho >> 1, r = rho & 1;                                 \
                goff = q * 4096 + (b0 + 32 * r) * 64 + l * 4;                  \
                soff = q * 128 + r * 64 + l * 4;                               \
            } else {                                                           \
                int rho2 = rho - 18;                                           \
                int r = rho2 >> 1, hh = rho2 & 1;                              \
                goff = 36864 + (b0 + 32 * r) * 128 + hh * 64 + l * 4;          \
                soff = 1152 + r * 128 + hh * 64 + l * 4;                       \
            }                                                                  \
            *reinterpret_cast<float4*>(nbuf + soff) =                          \
                *reinterpret_cast<const float4*>(nsrc + goff);                 \
        }                                                                      \
    }

    if (tid < 64) {
        h1[0][tid] = h1[1][tid] = h2[0][tid] = h2[1][tid] = 0.f;
        h3[0][tid] = h3[1][tid] = 0.f;
        prev[0][tid] = prev[1][tid] = 0.f;
    }
    if (tid < 128) { fwin[0][tid] = 0.f; fwin[1][tid] = 0.f; }
    STAGE_NOISE(0, tid, 384);
    __syncthreads();

#pragma unroll 1
    for (int t = 0; t < 100; t++) {
#pragma unroll 1
        for (int s = 0; s < 4; s++) {
            const int step = t * 4 + s;

            // ---- phase A: noise sub + prev, shift s3 (128 threads: j,r) ----
            if (tid < 128) {
                int j = tid & 63, r = tid >> 6;
                float sx = g_X[(t * 64 + b0 + 32 * r) * 256 + s * 64 + j];
                float olds = fwin[r][j];
                fwin[r][64 + j] = olds;                            // s3
                fwin[r][j] = clip1(sx + nbuf[r * 64 + j]);         // stream 0
                sfr[r][256 + j] = clip1(prev[r][j] + nbuf[128 + r * 64 + j]); // 1
            }
            __syncthreads();

            // ---- fw dense: 64 outs, 4-way k-split, shfl-fused tanh ----
            if (tid < 256) {
                int n = tid >> 2, kh = tid & 3;
                float2 v = dotp2<8>(g_wp + OFF_FW + kh * 8 * 64, n, 64,
                                    &fwin[0][kh * 32], &fwin[1][kh * 32]);
                v = red2_12(v);
                if (kh == 0) { tmp[0][n] = tanhf(v.x); tmp[1][n] = tanhf(v.y); }
            }
            __syncthreads();

            // ---- fw GLU: 64 outs, 4-way, shfl-fused; writes sfr[.][192+] ----
            if (tid < 256) {
                int n = tid >> 2, kh = tid & 3;
                float2 v = dotp2<4>(g_wp + OFF_FWGLU + kh * 4 * 64, n, 64,
                                    &tmp[0][kh * 16], &tmp[1][kh * 16]);
                v = red2_12(v);
                if (kh == 0) {
                    sfr[0][192 + n] = clip1(tmp[0][n] * sigm(v.x) + nbuf[256 + n]);
                    sfr[1][192 + n] = clip1(tmp[1][n] * sigm(v.y) + nbuf[256 + 64 + n]);
                }
            }
            __syncthreads();

            // ================= GRU blocks =================
            // gates: 384 thr, n = tid>>1 (0..191), kh = tid&1; shfl pre-reduce
#define GRU_GATES_1(WIHOFF, WHHOFF, H)                                         \
            {                                                                  \
                int n = tid >> 1, kh = tid & 1;                                \
                float2 gi = dotp2<16>(g_wp + (WIHOFF) + kh * 16 * 192, n, 192, \
                                      &sfr[0][192 + kh * 64], &sfr[1][192 + kh * 64]); \
                float2 gh = dotp2<8>(g_wp + (WHHOFF) + kh * 8 * 192, n, 192,   \
                                     &(H)[0][kh * 32], &(H)[1][kh * 32]);      \
                gi = red2_1(gi); gh = red2_1(gh);                              \
                if (kh == 0) { part_a[n] = gi; part_b[n] = gh; }               \
            }
#define GRU_GATES_2(WIHOFF, WHHOFF, GOFF, H)                                   \
            {                                                                  \
                int n = tid >> 1, kh = tid & 1;                                \
                const float* a0 = kh ? &sfr[0][256] : &sfr[0][GOFF];           \
                const float* a1 = kh ? &sfr[1][256] : &sfr[1][GOFF];           \
                float2 gi = dotp2<16>(g_wp + (WIHOFF) + kh * 16 * 192, n, 192, a0, a1); \
                float2 gh = dotp2<8>(g_wp + (WHHOFF) + kh * 8 * 192, n, 192,   \
                                     &(H)[0][kh * 32], &(H)[1][kh * 32]);      \
                gi = red2_1(gi); gh = red2_1(gh);                              \
                if (kh == 0) { part_a[n] = gi; part_b[n] = gh; }               \
            }
            // combine: 128 threads (j, r)
#define GRU_COMBINE(H, KH)                                                     \
            if (tid < 128) {                                                   \
                int j = tid & 63, r = tid >> 6;                                \
                const float* pa = reinterpret_cast<const float*>(part_a);      \
                const float* pb = reinterpret_cast<const float*>(part_b);      \
                float gir = pa[2 * j + r];                                     \
                float giz = pa[2 * (64 + j) + r];                              \
                float gin = pa[2 * (128 + j) + r];                             \
                float ghr = pb[2 * j + r];                                     \
                float ghz = pb[2 * (64 + j) + r];                              \
                float ghn = pb[2 * (128 + j) + r];                             \
                float hv = (H)[r][j];                                          \
                float rr = sigm(gir + ghr);                                    \
                float zz = sigm(giz + ghz);                                    \
                float nn = tanhf(gin + rr * ghn);                              \
                float nh = (1.0f - zz) * nn + zz * hv;                         \
                (H)[r][j] = nh;                                                \
                tmp[r][j] = clip1(nh + nbuf[(KH) * 128 + r * 64 + j]);         \
            }
            // GLU: 64 outs, 4-way, shfl-fused
#define GLU_PHASE(GLUOFF, DSTOFF, KG)                                          \
            if (tid < 256) {                                                   \
                int n = tid >> 2, kh = tid & 3;                                \
                float2 v = dotp2<4>(g_wp + (GLUOFF) + kh * 4 * 64, n, 64,      \
                                    &tmp[0][kh * 16], &tmp[1][kh * 16]);       \
                v = red2_12(v);                                                \
                if (kh == 0) {                                                 \
                    sfr[0][(DSTOFF) + n] =                                     \
                        clip1(tmp[0][n] * sigm(v.x) + nbuf[(KG) * 128 + n]);   \
                    sfr[1][(DSTOFF) + n] =                                     \
                        clip1(tmp[1][n] * sigm(v.y) + nbuf[(KG) * 128 + 64 + n]); \
                }                                                              \
            }

            // GRU1 (input = concat(fw, prevn), contiguous at sfr+192)
            GRU_GATES_1(OFF_WIH1, OFF_WHH1, h1);
            __syncthreads();
            GRU_COMBINE(h1, 3);
            __syncthreads();
            GLU_PHASE(OFF_GLU1, 0, 4);
            __syncthreads();

            // GRU2 (input = concat(g1 @ sfr+0, prevn @ sfr+256))
            GRU_GATES_2(OFF_WIH2, OFF_WHH2, 0, h2);
            __syncthreads();
            GRU_COMBINE(h2, 5);
            __syncthreads();
            GLU_PHASE(OFF_GLU2, 64, 6);
            __syncthreads();

            // GRU3 (input = concat(g2 @ sfr+64, prevn @ sfr+256))
            GRU_GATES_2(OFF_WIH3, OFF_WHH3, 64, h3);
            __syncthreads();
            GRU_COMBINE(h3, 7);
            __syncthreads();
            GLU_PHASE(OFF_GLU3, 128, 8);
            __syncthreads();

            // ---- skip dense: 128 outs, K4=80 split 27/27/26 (384 thr) ----
            {
                int n = tid & 127, seg = tid >> 7;
                if (seg == 0)
                    part_a[tid] = dotp2<27>(g_wp + OFF_SKIPD, n, 128,
                                            &sfr[0][0], &sfr[1][0]);
                else if (seg == 1)
                    part_a[tid] = dotp2<27>(g_wp + OFF_SKIPD + 27 * 128, n, 128,
                                            &sfr[0][108], &sfr[1][108]);
                else
                    part_a[tid] = dotp2<26>(g_wp + OFF_SKIPD + 54 * 128, n, 128,
                                            &sfr[0][216], &sfr[1][216]);
            }
            __syncthreads();
            if (tid < 128) {
                int n = tid;
                float dx = part_a[n].x + part_a[128 + n].x + part_a[256 + n].x;
                float dy = part_a[n].y + part_a[128 + n].y + part_a[256 + n].y;
                skb[0][n] = clip1(tanhf(dx) + nbuf[1152 + n]);       // stream 9
                skb[1][n] = clip1(tanhf(dy) + nbuf[1152 + 128 + n]);
            }
            __syncthreads();

            // ---- skip GLU: 128 outs, 2-way, shfl-fused ----
            if (tid < 256) {
                int n = tid >> 1, kh = tid & 1;
                float2 v = dotp2<16>(g_wp + OFF_SKIPG + kh * 16 * 128, n, 128,
                                     &skb[0][kh * 64], &skb[1][kh * 64]);
                v = red2_1(v);
                if (kh == 0) {
                    sk2[0][n] = skb[0][n] * sigm(v.x);
                    sk2[1][n] = skb[1][n] * sigm(v.y);
                }
            }
            __syncthreads();

            // ---- out: 64 outs, 4-way, shfl-fused; warps 8-11 stage noise ----
            if (tid < 256) {
                int n = tid >> 2, kh = tid & 3;
                float2 v = dotp2<8>(g_wp + OFF_OUT + kh * 8 * 64, n, 64,
                                    &sk2[0][kh * 32], &sk2[1][kh * 32]);
                v = red2_12(v);
                if (kh == 0) {
                    float ox = tanhf(v.x), oy = tanhf(v.y);
                    int base = t * 256 + s * 64 + n;
                    out[b0 * 25600 + base] = ox;
                    out[(b0 + 32) * 25600 + base] = oy;
                    prev[0][n] = ox; prev[1][n] = oy;
                }
            } else if (step < 399) {
                STAGE_NOISE(step + 1, tid - 256, 128);
            }
            __syncthreads();
        }
    }
#undef STAGE_NOISE
}

// ------------------------------- launcher ----------------------------------
extern "C" void kernel_launch(void* const* d_in, const int* in_sizes, int n_in,
                              void* d_out, int out_size) {
    const float* features = (const float*)d_in[0];
    const float* gfeat    = (const float*)d_in[1];
    const float* in_W1    = (const float*)d_in[2];
    const float* in_b1    = (const float*)d_in[3];
    const float* in_W2    = (const float*)d_in[4];
    const float* in_b2    = (const float*)d_in[5];
    const float* fw_W     = (const float*)d_in[6];
    const float* fw_glu_W = (const float*)d_in[7];
    const float* g1_Wih   = (const float*)d_in[8];
    const float* g1_Whh   = (const float*)d_in[9];
    const float* glu1_W   = (const float*)d_in[10];
    const float* g2_Wih   = (const float*)d_in[11];
    const float* g2_Whh   = (const float*)d_in[12];
    const float* glu2_W   = (const float*)d_in[13];
    const float* g3_Wih   = (const float*)d_in[14];
    const float* g3_Whh   = (const float*)d_in[15];
    const float* glu3_W   = (const float*)d_in[16];
    const float* skipd_W  = (const float*)d_in[17];
    const float* skipg_W  = (const float*)d_in[18];
    const float* out_W    = (const float*)d_in[19];
    float* out = (float*)d_out;

    // noise precomputation (partitionable threefry)
    gen_keys<<<(4000 + 127) / 128, 128>>>();
    gen_noise<<<dim3(176, 400), 256>>>();

    // input MLP (all frames)
    build_a1<<<12800, 256>>>(features, gfeat);
    gemm1<<<dim3(100, 8), 256>>>(in_W1, in_b1);
    gemm2<<<dim3(100, 4), 256>>>(in_W2, in_b2);

    // pack recurrent weights
    auto P = [](const float* src, int off, int N, int K) {
        int cnt = N * (K / 4);
        packw<<<(cnt + 255) / 256, 256>>>(src, off, N, K / 4);
    };
    P(fw_W,    OFF_FW,    64, 128);
    P(fw_glu_W,OFF_FWGLU, 64, 64);
    P(g1_Wih,  OFF_WIH1, 192, 128);
    P(g1_Whh,  OFF_WHH1, 192, 64);
    P(glu1_W,  OFF_GLU1,  64, 64);
    P(g2_Wih,  OFF_WIH2, 192, 128);
    P(g2_Whh,  OFF_WHH2, 192, 64);
    P(glu2_W,  OFF_GLU2,  64, 64);
    P(g3_Wih,  OFF_WIH3, 192, 128);
    P(g3_Whh,  OFF_WHH3, 192, 64);
    P(glu3_W,  OFF_GLU3,  64, 64);
    P(skipd_W, OFF_SKIPD,128, 320);
    P(skipg_W, OFF_SKIPG,128, 128);
    P(out_W,   OFF_OUT,   64, 128);

    // sequential recurrent pass
    fargan_rnn<<<32, 384>>>(out);
}

// round 8
// speedup vs baseline: 1.4694x; 1.4694x over previous
#include <cuda_runtime.h>
#include <stdint.h>
#include <stddef.h>

// ===========================================================================
// FARGAN vocoder. B=64, T=100, NSUB=4, S=64, HOP=256, IC=512.
// Stage 0: precompute ALL noise (partitionable threefry) -> g_nz
// Stage 1: input MLP for all frames (no recurrence)      -> g_X
// Stage 2: pack/transpose recurrent weights              -> g_wp
// Stage 3: sequential recurrent kernel, 32 CTAs x 384 thr, rows (b, b+32).
//          R6 skeleton (smem partial reductions) + f32x2 FMA inner loop.
// ===========================================================================

__device__ float g_A1[6400 * 512];
__device__ float g_H [6400 * 512];
__device__ float g_X [6400 * 256];
__device__ float4 g_wp[50176];       // packed transposed recurrent weights
__device__ uint2 g_kk[4000];
__device__ float g_nz[18022400];     // 400 steps * 45056 noise values

// packed-weight offsets (float4 units)
#define OFF_FW     0
#define OFF_FWGLU  2048
#define OFF_WIH1   3072
#define OFF_WHH1   9216
#define OFF_GLU1   12288
#define OFF_WIH2   13312
#define OFF_WHH2   19456
#define OFF_GLU2   22528
#define OFF_WIH3   23552
#define OFF_WHH3   29696
#define OFF_GLU3   32768
#define OFF_SKIPD  33792
#define OFF_SKIPG  44032
#define OFF_OUT    48128

// ----------------------------- threefry2x32 --------------------------------
__device__ __forceinline__ uint32_t rotl32(uint32_t v, int s) {
    return (v << s) | (v >> (32 - s));
}
__device__ __forceinline__ uint2 tf2x32(uint2 key, uint2 ctr) {
    uint32_t ks0 = key.x, ks1 = key.y;
    uint32_t ks2 = ks0 ^ ks1 ^ 0x1BD11BDAu;
    uint32_t x0 = ctr.x + ks0, x1 = ctr.y + ks1;
#define TFR(r) { x0 += x1; x1 = rotl32(x1, (r)); x1 ^= x0; }
    TFR(13) TFR(15) TFR(26) TFR(6)   x0 += ks1; x1 += ks2 + 1u;
    TFR(17) TFR(29) TFR(16) TFR(24)  x0 += ks2; x1 += ks0 + 2u;
    TFR(13) TFR(15) TFR(26) TFR(6)   x0 += ks0; x1 += ks1 + 3u;
    TFR(17) TFR(29) TFR(16) TFR(24)  x0 += ks1; x1 += ks2 + 4u;
    TFR(13) TFR(15) TFR(26) TFR(6)   x0 += ks2; x1 += ks0 + 5u;
#undef TFR
    return make_uint2(x0, x1);
}
__device__ __forceinline__ float nzf(uint32_t r) {
    float u = __uint_as_float((r >> 9) | 0x3f800000u) - 1.0f;
    return (u - 0.5f) * (1.0f / 127.0f);
}
__device__ __forceinline__ float clip1(float v) { return fminf(fmaxf(v, -1.0f), 1.0f); }
__device__ __forceinline__ float sigm(float x) { return 1.0f / (1.0f + expf(-x)); }

// ------------------------- noise precomputation ----------------------------
__global__ void gen_keys() {
    int idx = blockIdx.x * 128 + threadIdx.x;
    if (idx >= 4000) return;
    int step = idx / 10, q = idx % 10;
    uint2 fkey = tf2x32(make_uint2(0u, 1u), make_uint2(0u, (uint32_t)step));
    g_kk[idx] = tf2x32(fkey, make_uint2(0u, (uint32_t)q));
}
__global__ void gen_noise() {
    int rem = blockIdx.x * 256 + threadIdx.x;   // [0, 45056)
    int step = blockIdx.y;
    int q, f;
    if (rem < 36864) { q = rem >> 12; f = rem & 4095; }
    else             { q = 9;         f = rem - 36864; }
    uint2 kk = g_kk[step * 10 + q];
    uint2 c = tf2x32(kk, make_uint2(0u, (uint32_t)f));
    g_nz[(size_t)step * 45056 + rem] = nzf(c.x ^ c.y);
}

// ----------------------------- input MLP -----------------------------------
__global__ void build_a1(const float* __restrict__ feats, const float* __restrict__ gf) {
    int idx = blockIdx.x * blockDim.x + threadIdx.x;
    if (idx >= 6400 * 512) return;
    int row = idx >> 9;
    int k = idx & 511;
    int t = row >> 6, b = row & 63;
    float v;
    if (k < 256) v = feats[(b * 256 + k) * 100 + t];
    else         v = gf[b * 256 + (k - 256)];
    g_A1[idx] = v;
}

template <int ACT>
__device__ __forceinline__ void gemm_body(const float* __restrict__ A,
                                          const float* __restrict__ W,
                                          const float* __restrict__ bias,
                                          float* __restrict__ out, int N, int K) {
    __shared__ float As[64][17];
    __shared__ float Bs[16][65];
    const int bm = blockIdx.x * 64, bn = blockIdx.y * 64;
    const int tx = threadIdx.x & 15, ty = threadIdx.x >> 4;
    float acc[4][4] = {};
    for (int k0 = 0; k0 < K; k0 += 16) {
#pragma unroll
        for (int i = 0; i < 4; i++) {
            int lin = threadIdx.x + i * 256;
            int r = lin >> 4, c = lin & 15;
            As[r][c] = A[(bm + r) * K + k0 + c];
            Bs[c][r] = W[(bn + r) * K + k0 + c];
        }
        __syncthreads();
#pragma unroll
        for (int kk = 0; kk < 16; kk++) {
            float a[4], bb[4];
#pragma unroll
            for (int i = 0; i < 4; i++) a[i] = As[ty * 4 + i][kk];
#pragma unroll
            for (int j = 0; j < 4; j++) bb[j] = Bs[kk][tx * 4 + j];
#pragma unroll
            for (int i = 0; i < 4; i++)
#pragma unroll
                for (int j = 0; j < 4; j++)
                    acc[i][j] = fmaf(a[i], bb[j], acc[i][j]);
        }
        __syncthreads();
    }
#pragma unroll
    for (int i = 0; i < 4; i++) {
        int m = bm + ty * 4 + i;
#pragma unroll
        for (int j = 0; j < 4; j++) {
            int nn = bn + tx * 4 + j;
            float v = acc[i][j] + bias[nn];
            if (ACT) v = tanhf(v);
            out[m * N + nn] = v;
        }
    }
}
__global__ __launch_bounds__(256) void gemm1(const float* __restrict__ W,
                                             const float* __restrict__ b) {
    gemm_body<1>(g_A1, W, b, g_H, 512, 512);
}
__global__ __launch_bounds__(256) void gemm2(const float* __restrict__ W,
                                             const float* __restrict__ b) {
    gemm_body<0>(g_H, W, b, g_X, 256, 512);
}

// ----------------------- weight transpose/pack -----------------------------
__global__ void packw(const float* __restrict__ src, int off, int N, int K4) {
    int idx = blockIdx.x * blockDim.x + threadIdx.x;
    if (idx >= N * K4) return;
    int n = idx % N, kq = idx / N;
    const float* s = src + n * (K4 * 4) + 4 * kq;
    g_wp[off + idx] = make_float4(s[0], s[1], s[2], s[3]);
}

// ---------------------- packed f32x2 dual-row dot --------------------------
// Lanes of each f32x2 = (k, k+1) of the SAME batch row, so both the weight
// pair and the activation pair come natively from 128-bit loads (no MOVs).
// Per 4 k's: 1 LDG.128 + 2 broadcast LDS.128 + 4 FFMA2 (was 8 FFMA in R6).
// x0/x1 must be 16B-aligned.
__device__ __forceinline__ void fma2(uint64_t& acc, uint64_t w, uint64_t x) {
    asm("fma.rn.f32x2 %0, %1, %2, %0;" : "+l"(acc) : "l"(w), "l"(x));
}
template <int LEN>
__device__ __forceinline__ float2 dotp2(const float4* __restrict__ wp, int n, int N,
                                        const float* __restrict__ x0,
                                        const float* __restrict__ x1) {
    const ulonglong2* wv = reinterpret_cast<const ulonglong2*>(wp);
    const ulonglong2* xa = reinterpret_cast<const ulonglong2*>(x0);
    const ulonglong2* xb = reinterpret_cast<const ulonglong2*>(x1);
    uint64_t a0 = 0ull, a1 = 0ull, b0 = 0ull, b1 = 0ull;   // bits 0 == (0.f,0.f)
#pragma unroll
    for (int i = 0; i < LEN; i++) {
        ulonglong2 w = wv[i * N + n];
        ulonglong2 p = xa[i];
        ulonglong2 q = xb[i];
        fma2(a0, w.x, p.x); fma2(a1, w.y, p.y);
        fma2(b0, w.x, q.x); fma2(b1, w.y, q.y);
    }
    uint64_t s0, s1;
    asm("add.rn.f32x2 %0, %1, %2;" : "=l"(s0) : "l"(a0), "l"(a1));
    asm("add.rn.f32x2 %0, %1, %2;" : "=l"(s1) : "l"(b0), "l"(b1));
    uint32_t lo0, hi0, lo1, hi1;
    asm("mov.b64 {%0,%1}, %2;" : "=r"(lo0), "=r"(hi0) : "l"(s0));
    asm("mov.b64 {%0,%1}, %2;" : "=r"(lo1), "=r"(hi1) : "l"(s1));
    return make_float2(__uint_as_float(lo0) + __uint_as_float(hi0),
                       __uint_as_float(lo1) + __uint_as_float(hi1));
}

// --------------------------- recurrent kernel ------------------------------
__global__ __launch_bounds__(384, 1) void fargan_rnn(float* __restrict__ out) {
    const int tid = threadIdx.x;
    const int b0 = blockIdx.x;            // batch rows b0 and b0+32

    // split-row activation arrays (16B-aligned, row stride multiple of 16B)
    __shared__ __align__(16) float sfr[2][320];    // [g1|g2|g3|fw|prevn]
    __shared__ __align__(16) float fwin[2][128];   // [sub_noised | s3]
    __shared__ __align__(16) float tmp[2][64];
    __shared__ __align__(16) float h1[2][64], h2[2][64], h3[2][64];
    __shared__ __align__(16) float prev[2][64];
    __shared__ __align__(16) float skb[2][128];
    __shared__ __align__(16) float sk2[2][128];
    __shared__ __align__(16) float2 part_a[384], part_b[384];
    __shared__ __align__(16) float nbuf[1408];

    // stage one step's noise into nbuf:
    //  nbuf: q<9 -> q*128 + r*64 + j ; q=9 -> 1152 + r*128 + j
#define STAGE_NOISE(STEP, BASE, STRIDE)                                        \
    {                                                                          \
        const float* nsrc = g_nz + (size_t)(STEP) * 45056;                     \
        for (int c = (BASE); c < 352; c += (STRIDE)) {                         \
            int rho = c >> 4, l = c & 15;                                      \
            int goff, soff;                                                    \
            if (rho < 18) {                                                    \
                int q = rho >> 1, r = rho & 1;                                 \
                goff = q * 4096 + (b0 + 32 * r) * 64 + l * 4;                  \
                soff = q * 128 + r * 64 + l * 4;                               \
            } else {                                                           \
                int rho2 = rho - 18;                                           \
                int r = rho2 >> 1, hh = rho2 & 1;                              \
                goff = 36864 + (b0 + 32 * r) * 128 + hh * 64 + l * 4;          \
                soff = 1152 + r * 128 + hh * 64 + l * 4;                       \
            }                                                                  \
            *reinterpret_cast<float4*>(nbuf + soff) =                          \
                *reinterpret_cast<const float4*>(nsrc + goff);                 \
        }                                                                      \
    }

    if (tid < 64) {
        h1[0][tid] = h1[1][tid] = h2[0][tid] = h2[1][tid] = 0.f;
        h3[0][tid] = h3[1][tid] = 0.f;
        prev[0][tid] = prev[1][tid] = 0.f;
    }
    if (tid < 128) { fwin[0][tid] = 0.f; fwin[1][tid] = 0.f; }
    STAGE_NOISE(0, tid, 384);
    __syncthreads();

#pragma unroll 1
    for (int t = 0; t < 100; t++) {
#pragma unroll 1
        for (int s = 0; s < 4; s++) {
            const int step = t * 4 + s;

            // ---- phase A: noise sub + prev, shift s3 (128 threads: j,r) ----
            if (tid < 128) {
                int j = tid & 63, r = tid >> 6;
                float sx = g_X[(t * 64 + b0 + 32 * r) * 256 + s * 64 + j];
                float olds = fwin[r][j];
                fwin[r][64 + j] = olds;                              // s3
                fwin[r][j] = clip1(sx + nbuf[r * 64 + j]);           // stream 0
                sfr[r][256 + j] = clip1(prev[r][j] + nbuf[128 + r * 64 + j]); // 1
            }
            __syncthreads();

            // ---- fw dense: 64 outs, K4=32, 4-way k-split (256 threads) ----
            if (tid < 256) {
                int n = tid & 63, kh = tid >> 6;
                part_a[tid] = dotp2<8>(g_wp + OFF_FW + kh * 8 * 64, n, 64,
                                       &fwin[0][kh * 32], &fwin[1][kh * 32]);
            }
            __syncthreads();
            if (tid < 64) {
                int n = tid;
                float dx = part_a[n].x + part_a[64 + n].x + part_a[128 + n].x + part_a[192 + n].x;
                float dy = part_a[n].y + part_a[64 + n].y + part_a[128 + n].y + part_a[192 + n].y;
                tmp[0][n] = tanhf(dx); tmp[1][n] = tanhf(dy);
            }
            __syncthreads();

            // ---- fw GLU: 64 outs, K4=16, 4-way split ----
            if (tid < 256) {
                int n = tid & 63, kh = tid >> 6;
                part_a[tid] = dotp2<4>(g_wp + OFF_FWGLU + kh * 4 * 64, n, 64,
                                       &tmp[0][kh * 16], &tmp[1][kh * 16]);
            }
            __syncthreads();
            if (tid < 64) {
                int n = tid;
                float dx = part_a[n].x + part_a[64 + n].x + part_a[128 + n].x + part_a[192 + n].x;
                float dy = part_a[n].y + part_a[64 + n].y + part_a[128 + n].y + part_a[192 + n].y;
                sfr[0][192 + n] = clip1(tmp[0][n] * sigm(dx) + nbuf[256 + n]);   // stream 2
                sfr[1][192 + n] = clip1(tmp[1][n] * sigm(dy) + nbuf[256 + 64 + n]);
            }
            __syncthreads();

            // ================= GRU blocks =================
            // gates: 384 threads, n = tid%192, kh = tid/192 (2-way k-split)
#define GRU_GATES_1(WIHOFF, WHHOFF, H)                                         \
            {                                                                  \
                int n = tid % 192, kh = tid / 192;                             \
                part_a[tid] = dotp2<16>(g_wp + (WIHOFF) + kh * 16 * 192, n, 192, \
                                        &sfr[0][192 + kh * 64], &sfr[1][192 + kh * 64]); \
                part_b[tid] = dotp2<8>(g_wp + (WHHOFF) + kh * 8 * 192, n, 192, \
                                       &(H)[0][kh * 32], &(H)[1][kh * 32]);    \
            }
#define GRU_GATES_2(WIHOFF, WHHOFF, GOFF, H)                                   \
            {                                                                  \
                int n = tid % 192, kh = tid / 192;                             \
                const float* a0 = kh ? &sfr[0][256] : &sfr[0][GOFF];           \
                const float* a1 = kh ? &sfr[1][256] : &sfr[1][GOFF];           \
                part_a[tid] = dotp2<16>(g_wp + (WIHOFF) + kh * 16 * 192, n, 192, a0, a1); \
                part_b[tid] = dotp2<8>(g_wp + (WHHOFF) + kh * 8 * 192, n, 192, \
                                       &(H)[0][kh * 32], &(H)[1][kh * 32]);    \
            }
            // combine: 128 threads (j, r)
#define GRU_COMBINE(H, KH)                                                     \
            if (tid < 128) {                                                   \
                int j = tid & 63, r = tid >> 6;                                \
                const float* pa = reinterpret_cast<const float*>(part_a);      \
                const float* pb = reinterpret_cast<const float*>(part_b);      \
                float gir = pa[2 * j + r]         + pa[2 * (192 + j) + r];     \
                float giz = pa[2 * (64 + j) + r]  + pa[2 * (256 + j) + r];     \
                float gin = pa[2 * (128 + j) + r] + pa[2 * (320 + j) + r];     \
                float ghr = pb[2 * j + r]         + pb[2 * (192 + j) + r];     \
                float ghz = pb[2 * (64 + j) + r]  + pb[2 * (256 + j) + r];     \
                float ghn = pb[2 * (128 + j) + r] + pb[2 * (320 + j) + r];     \
                float hv = (H)[r][j];                                          \
                float rr = sigm(gir + ghr);                                    \
                float zz = sigm(giz + ghz);                                    \
                float nn = tanhf(gin + rr * ghn);                              \
                float nh = (1.0f - zz) * nn + zz * hv;                         \
                (H)[r][j] = nh;                                                \
                tmp[r][j] = clip1(nh + nbuf[(KH) * 128 + r * 64 + j]);         \
            }
            // GLU: 64 outs, K4=16, 4-way split
#define GLU_PHASE(GLUOFF, DSTOFF, KG)                                          \
            if (tid < 256) {                                                   \
                int n = tid & 63, kh = tid >> 6;                               \
                part_a[tid] = dotp2<4>(g_wp + (GLUOFF) + kh * 4 * 64, n, 64,   \
                                       &tmp[0][kh * 16], &tmp[1][kh * 16]);    \
            }                                                                  \
            __syncthreads();                                                   \
            if (tid < 64) {                                                    \
                int n = tid;                                                   \
                float dx = part_a[n].x + part_a[64 + n].x + part_a[128 + n].x + part_a[192 + n].x; \
                float dy = part_a[n].y + part_a[64 + n].y + part_a[128 + n].y + part_a[192 + n].y; \
                sfr[0][(DSTOFF) + n] =                                         \
                    clip1(tmp[0][n] * sigm(dx) + nbuf[(KG) * 128 + n]);        \
                sfr[1][(DSTOFF) + n] =                                         \
                    clip1(tmp[1][n] * sigm(dy) + nbuf[(KG) * 128 + 64 + n]);   \
            }

            // GRU1 (input = concat(fw, prevn), contiguous at sfr+192)
            GRU_GATES_1(OFF_WIH1, OFF_WHH1, h1);
            __syncthreads();
            GRU_COMBINE(h1, 3);
            __syncthreads();
            GLU_PHASE(OFF_GLU1, 0, 4);
            __syncthreads();

            // GRU2 (input = concat(g1 @ sfr+0, prevn @ sfr+256))
            GRU_GATES_2(OFF_WIH2, OFF_WHH2, 0, h2);
            __syncthreads();
            GRU_COMBINE(h2, 5);
            __syncthreads();
            GLU_PHASE(OFF_GLU2, 64, 6);
            __syncthreads();

            // GRU3 (input = concat(g2 @ sfr+64, prevn @ sfr+256))
            GRU_GATES_2(OFF_WIH3, OFF_WHH3, 64, h3);
            __syncthreads();
            GRU_COMBINE(h3, 7);
            __syncthreads();
            GLU_PHASE(OFF_GLU3, 128, 8);
            __syncthreads();

            // ---- skip dense: 128 outs, K4=80 split 27/27/26 (384 thr) ----
            {
                int n = tid & 127, seg = tid >> 7;
                if (seg == 0)
                    part_a[tid] = dotp2<27>(g_wp + OFF_SKIPD, n, 128,
                                            &sfr[0][0], &sfr[1][0]);
                else if (seg == 1)
                    part_a[tid] = dotp2<27>(g_wp + OFF_SKIPD + 27 * 128, n, 128,
                                            &sfr[0][108], &sfr[1][108]);
                else
                    part_a[tid] = dotp2<26>(g_wp + OFF_SKIPD + 54 * 128, n, 128,
                                            &sfr[0][216], &sfr[1][216]);
            }
            __syncthreads();
            if (tid < 128) {
                int n = tid;
                float dx = part_a[n].x + part_a[128 + n].x + part_a[256 + n].x;
                float dy = part_a[n].y + part_a[128 + n].y + part_a[256 + n].y;
                skb[0][n] = clip1(tanhf(dx) + nbuf[1152 + n]);       // stream 9
                skb[1][n] = clip1(tanhf(dy) + nbuf[1152 + 128 + n]);
            }
            __syncthreads();

            // ---- skip GLU: 128 outs, K4=32, 2-way split (256 thr) ----
            if (tid < 256) {
                int n = tid & 127, kh = tid >> 7;
                part_a[tid] = dotp2<16>(g_wp + OFF_SKIPG + kh * 16 * 128, n, 128,
                                        &skb[0][kh * 64], &skb[1][kh * 64]);
            }
            __syncthreads();
            if (tid < 128) {
                int n = tid;
                float dx = part_a[n].x + part_a[128 + n].x;
                float dy = part_a[n].y + part_a[128 + n].y;
                sk2[0][n] = skb[0][n] * sigm(dx);
                sk2[1][n] = skb[1][n] * sigm(dy);
            }
            __syncthreads();

            // ---- out: 64 outs, K4=32, 4-way; warps 8-11 stage next noise ----
            if (tid < 256) {
                int n = tid & 63, kh = tid >> 6;
                part_a[tid] = dotp2<8>(g_wp + OFF_OUT + kh * 8 * 64, n, 64,
                                       &sk2[0][kh * 32], &sk2[1][kh * 32]);
            } else if (step < 399) {
                STAGE_NOISE(step + 1, tid - 256, 128);
            }
            __syncthreads();
            if (tid < 64) {
                int n = tid;
                float dx = part_a[n].x + part_a[64 + n].x + part_a[128 + n].x + part_a[192 + n].x;
                float dy = part_a[n].y + part_a[64 + n].y + part_a[128 + n].y + part_a[192 + n].y;
                float ox = tanhf(dx), oy = tanhf(dy);
                int base = t * 256 + s * 64 + n;
                out[b0 * 25600 + base] = ox;
                out[(b0 + 32) * 25600 + base] = oy;
                prev[0][n] = ox; prev[1][n] = oy;
            }
            __syncthreads();
        }
    }
#undef STAGE_NOISE
}

// ------------------------------- launcher ----------------------------------
extern "C" void kernel_launch(void* const* d_in, const int* in_sizes, int n_in,
                              void* d_out, int out_size) {
    const float* features = (const float*)d_in[0];
    const float* gfeat    = (const float*)d_in[1];
    const float* in_W1    = (const float*)d_in[2];
    const float* in_b1    = (const float*)d_in[3];
    const float* in_W2    = (const float*)d_in[4];
    const float* in_b2    = (const float*)d_in[5];
    const float* fw_W     = (const float*)d_in[6];
    const float* fw_glu_W = (const float*)d_in[7];
    const float* g1_Wih   = (const float*)d_in[8];
    const float* g1_Whh   = (const float*)d_in[9];
    const float* glu1_W   = (const float*)d_in[10];
    const float* g2_Wih   = (const float*)d_in[11];
    const float* g2_Whh   = (const float*)d_in[12];
    const float* glu2_W   = (const float*)d_in[13];
    const float* g3_Wih   = (const float*)d_in[14];
    const float* g3_Whh   = (const float*)d_in[15];
    const float* glu3_W   = (const float*)d_in[16];
    const float* skipd_W  = (const float*)d_in[17];
    const float* skipg_W  = (const float*)d_in[18];
    const float* out_W    = (const float*)d_in[19];
    float* out = (float*)d_out;

    // noise precomputation (partitionable threefry)
    gen_keys<<<(4000 + 127) / 128, 128>>>();
    gen_noise<<<dim3(176, 400), 256>>>();

    // input MLP (all frames)
    build_a1<<<12800, 256>>>(features, gfeat);
    gemm1<<<dim3(100, 8), 256>>>(in_W1, in_b1);
    gemm2<<<dim3(100, 4), 256>>>(in_W2, in_b2);

    // pack recurrent weights
    auto P = [](const float* src, int off, int N, int K) {
        int cnt = N * (K / 4);
        packw<<<(cnt + 255) / 256, 256>>>(src, off, N, K / 4);
    };
    P(fw_W,    OFF_FW,    64, 128);
    P(fw_glu_W,OFF_FWGLU, 64, 64);
    P(g1_Wih,  OFF_WIH1, 192, 128);
    P(g1_Whh,  OFF_WHH1, 192, 64);
    P(glu1_W,  OFF_GLU1,  64, 64);
    P(g2_Wih,  OFF_WIH2, 192, 128);
    P(g2_Whh,  OFF_WHH2, 192, 64);
    P(glu2_W,  OFF_GLU2,  64, 64);
    P(g3_Wih,  OFF_WIH3, 192, 128);
    P(g3_Whh,  OFF_WHH3, 192, 64);
    P(glu3_W,  OFF_GLU3,  64, 64);
    P(skipd_W, OFF_SKIPD,128, 320);
    P(skipg_W, OFF_SKIPG,128, 128);
    P(out_W,   OFF_OUT,   64, 128);

    // sequential recurrent pass
    fargan_rnn<<<32, 384>>>(out);
}